// round 5
// baseline (speedup 1.0000x reference)
#include <cuda_runtime.h>

#define NFLAT 4096
#define CH    32
#define CIN   64
#define BATCH 4

// Scratch (allocation-free rule: __device__ globals)
__device__ float gQ[BATCH * CH * NFLAT];   // natural [b][o][hw]; flat == q[b][n][c]
__device__ float gK[BATCH * CH * NFLAT];   // [b][c][m]
__device__ float gV[BATCH * CH * NFLAT];   // flat == v[b][m][c]
__device__ float gY[BATCH * NFLAT * CH];   // [b][n][c]; flat == y2[b][ci][hw]

// ---------------------------------------------------------------------------
// Kernel 1: three 1x1 convs (q, k, v). Output-channel dim split across
// blockIdx.z (16 oc per block) to raise occupancy (was 12%, regs=170).
// ---------------------------------------------------------------------------
__global__ __launch_bounds__(256) void qkv_kernel(
    const float* __restrict__ x,
    const float* __restrict__ w1, const float* __restrict__ b1,
    const float* __restrict__ w2, const float* __restrict__ b2,
    const float* __restrict__ w3, const float* __restrict__ b3)
{
    __shared__ float ws[16 * CIN];
    __shared__ float bs[16];
    int conv = blockIdx.y;
    const float* w    = (conv == 0) ? w1 : (conv == 1) ? w2 : w3;
    const float* bias = (conv == 0) ? b1 : (conv == 1) ? b2 : b3;
    float* o          = (conv == 0) ? gQ : (conv == 1) ? gK : gV;
    int ocb = blockIdx.z * 16;

    int t = threadIdx.x;
    for (int i = t; i < 16 * CIN; i += 256) ws[i] = w[ocb * CIN + i];
    if (t < 16) bs[t] = bias[ocb + t];
    __syncthreads();

    int idx = blockIdx.x * 256 + t;      // (b, hw)
    int b = idx >> 12, hw = idx & 4095;
    const float* xp = x + b * (CIN * NFLAT) + hw;

    float acc[16];
#pragma unroll
    for (int oc = 0; oc < 16; oc++) acc[oc] = bs[oc];

#pragma unroll 8
    for (int c = 0; c < CIN; c++) {
        float xv = xp[c * NFLAT];
#pragma unroll
        for (int oc = 0; oc < 16; oc++) acc[oc] += ws[oc * CIN + c] * xv;
    }

    float* op = o + b * (CH * NFLAT) + ocb * NFLAT + hw;
#pragma unroll
    for (int oc = 0; oc < 16; oc++) op[oc * NFLAT] = acc[oc];
}

// ---------------------------------------------------------------------------
// TF32 split helpers + mma.sync wrapper
// ---------------------------------------------------------------------------
__device__ __forceinline__ void split_tf32(float x, unsigned& hi, unsigned& lo)
{
    unsigned h = __float_as_uint(x) & 0xFFFFE000u;   // keep tf32 mantissa bits
    hi = h;
    lo = __float_as_uint(x - __uint_as_float(h));    // exact residual
}

__device__ __forceinline__ void mma_tf32(float* d, const unsigned* a,
                                         unsigned b0, unsigned b1)
{
    asm volatile(
        "mma.sync.aligned.m16n8k8.row.col.f32.tf32.tf32.f32 "
        "{%0,%1,%2,%3}, {%4,%5,%6,%7}, {%8,%9}, {%0,%1,%2,%3};\n"
        : "+f"(d[0]), "+f"(d[1]), "+f"(d[2]), "+f"(d[3])
        : "r"(a[0]), "r"(a[1]), "r"(a[2]), "r"(a[3]), "r"(b0), "r"(b1));
}

// ---------------------------------------------------------------------------
// Kernel 2: fused QK -> batch-softmax -> PV on tensor cores (3xTF32 split).
// CTA: 32 n-rows for ALL 4 batches; 8 warps = (batch b, 16-row half h).
// m-chunk = 64. K/V/P staged in smem in exact mma fragment order.
// ---------------------------------------------------------------------------
#define KF_OFF 0                    // [4b][8 mt][4 ks][64]   = 8192 floats
#define VF_OFF 8192                 // [4b][4 ct][8 ks][64]   = 8192
#define PF_OFF 16384                // [4b][2 hh][8 ks][128]  = 8192
#define SS_OFF 24576                // [4b][32 li][68]        = 8704
#define SSTR  68
#define SSLAB (32 * SSTR)
#define SM_FLOATS (24576 + 4 * SSLAB)
#define SM_BYTES  (SM_FLOATS * 4)   // 133120 B

__global__ __launch_bounds__(256, 1) void attn_kernel()
{
    extern __shared__ float sm[];
    float* kf = sm + KF_OFF;
    float* vf = sm + VF_OFF;
    float* pf = sm + PF_OFF;
    float* ss = sm + SS_OFF;

    int t    = threadIdx.x;
    int w    = t >> 5;
    int lane = t & 31;
    int g    = lane >> 2;           // groupID
    int tg   = lane & 3;            // threadID in group
    int bb   = w >> 1;              // batch this warp computes
    int hh   = w & 1;               // 16-row half
    int n0   = blockIdx.x * 32;

    // ---- Q fragments: load once, split to tf32 hi/lo, keep in registers ----
    unsigned qhi[4][4], qlo[4][4];
    {
        const float* qb = gQ + bb * (CH * NFLAT) + (n0 + hh * 16) * CH;
#pragma unroll
        for (int ks = 0; ks < 4; ks++) {
            split_tf32(qb[ g      * CH + ks * 8 + tg    ], qhi[ks][0], qlo[ks][0]);
            split_tf32(qb[(g + 8) * CH + ks * 8 + tg    ], qhi[ks][1], qlo[ks][1]);
            split_tf32(qb[ g      * CH + ks * 8 + tg + 4], qhi[ks][2], qlo[ks][2]);
            split_tf32(qb[(g + 8) * CH + ks * 8 + tg + 4], qhi[ks][3], qlo[ks][3]);
        }
    }

    // ---- output accumulators: 16n x 32c per warp = 4 ctiles ----
    float yacc[4][4];
#pragma unroll
    for (int ct = 0; ct < 4; ct++)
#pragma unroll
        for (int r = 0; r < 4; r++) yacc[ct][r] = 0.0f;

    // loader-role constants
    int ldb   = w >> 1;             // batch this warp loads
    int ldh   = w & 1;              // half (16 c-rows for K / 32 m-rows for V)
    // softmax-role constants
    int sli = t >> 3;               // row 0..31
    int smb = (t & 7) * 8;          // 8 consecutive m

    for (int m0 = 0; m0 < NFLAT; m0 += 64) {
        __syncthreads();            // prev chunk fully consumed

        // ---------------- load K chunk into fragment order ----------------
        {
            const float* kg = gK + ldb * (CH * NFLAT) + m0;
            int coff = (lane >> 4);            // 0/1
            int mf   = (lane & 15) * 4;
#pragma unroll
            for (int i = 0; i < 8; i++) {
                int c = ldh * 16 + i * 2 + coff;
                float4 vv = *(const float4*)(kg + c * NFLAT + mf);
                int ks = c >> 3, reg = (c & 7) >> 2, ctg = c & 3;
                const float* pv = (const float*)&vv;
#pragma unroll
                for (int u = 0; u < 4; u++) {
                    int m = mf + u;
                    kf[((ldb * 8 + (m >> 3)) * 4 + ks) * 64 +
                       ((m & 7) * 4 + ctg) * 2 + reg] = pv[u];
                }
            }
        }
        // ---------------- load V chunk into fragment order ----------------
        {
            const float* vg = gV + ldb * (CH * NFLAT) + (m0 + ldh * 32) * CH;
            int moff = lane >> 3;              // 0..3
            int cf   = (lane & 7) * 4;
#pragma unroll
            for (int i = 0; i < 8; i++) {
                int m  = i * 4 + moff;
                float4 vv = *(const float4*)(vg + m * CH + cf);
                int mm = ldh * 32 + m;         // j within chunk 0..63
                int ks = mm >> 3, reg = (mm & 7) >> 2, jtg = mm & 3;
                const float* pv = (const float*)&vv;
#pragma unroll
                for (int u = 0; u < 4; u++) {
                    int c = cf + u;
                    vf[((ldb * 4 + (c >> 3)) * 8 + ks) * 64 +
                       ((c & 7) * 4 + jtg) * 2 + reg] = pv[u];
                }
            }
        }
        __syncthreads();

        // ---------------- QK (split tf32: hi*hi + hi*lo + lo*hi) ----------
        float sacc[8][4];
#pragma unroll
        for (int mt = 0; mt < 8; mt++)
#pragma unroll
            for (int r = 0; r < 4; r++) sacc[mt][r] = 0.0f;

#pragma unroll
        for (int ks = 0; ks < 4; ks++) {
#pragma unroll
            for (int mt = 0; mt < 8; mt++) {
                float2 kv = *(const float2*)(kf + ((bb * 8 + mt) * 4 + ks) * 64 + lane * 2);
                unsigned bh0, bl0, bh1, bl1;
                split_tf32(kv.x, bh0, bl0);
                split_tf32(kv.y, bh1, bl1);
                mma_tf32(sacc[mt], qhi[ks], bh0, bh1);
                mma_tf32(sacc[mt], qhi[ks], bl0, bl1);
                mma_tf32(sacc[mt], qlo[ks], bh0, bh1);
            }
        }
        // store S for softmax
        {
            float* ssb = ss + bb * SSLAB + (hh * 16) * SSTR;
#pragma unroll
            for (int mt = 0; mt < 8; mt++) {
                *(float2*)(ssb +  g      * SSTR + mt * 8 + tg * 2) =
                    make_float2(sacc[mt][0], sacc[mt][1]);
                *(float2*)(ssb + (g + 8) * SSTR + mt * 8 + tg * 2) =
                    make_float2(sacc[mt][2], sacc[mt][3]);
            }
        }
        __syncthreads();

        // ---------------- softmax across the 4 batches --------------------
        {
            float ev[4][8];
#pragma unroll
            for (int b = 0; b < 4; b++) {
                float4 A = *(const float4*)(ss + b * SSLAB + sli * SSTR + smb);
                float4 B = *(const float4*)(ss + b * SSLAB + sli * SSTR + smb + 4);
                ev[b][0] = A.x; ev[b][1] = A.y; ev[b][2] = A.z; ev[b][3] = A.w;
                ev[b][4] = B.x; ev[b][5] = B.y; ev[b][6] = B.z; ev[b][7] = B.w;
            }
            int hh2  = sli >> 4;
            int l15  = sli & 15;
#pragma unroll
            for (int u = 0; u < 8; u++) {
                int m    = smb + u;
                int lane2 = (l15 & 7) * 4 + (m & 3);
                int r     = (l15 >> 3) | (((m >> 2) & 1) << 1);
                int ks    = m >> 3;
                float mx = fmaxf(fmaxf(ev[0][u], ev[1][u]), fmaxf(ev[2][u], ev[3][u]));
                float e0 = __expf(ev[0][u] - mx);
                float e1 = __expf(ev[1][u] - mx);
                float e2 = __expf(ev[2][u] - mx);
                float e3 = __expf(ev[3][u] - mx);
                float inv = 1.0f / (e0 + e1 + e2 + e3);
                pf[((0 * 2 + hh2) * 8 + ks) * 128 + lane2 * 4 + r] = e0 * inv;
                pf[((1 * 2 + hh2) * 8 + ks) * 128 + lane2 * 4 + r] = e1 * inv;
                pf[((2 * 2 + hh2) * 8 + ks) * 128 + lane2 * 4 + r] = e2 * inv;
                pf[((3 * 2 + hh2) * 8 + ks) * 128 + lane2 * 4 + r] = e3 * inv;
            }
        }
        __syncthreads();

        // ---------------- PV (split tf32) ---------------------------------
#pragma unroll
        for (int ks = 0; ks < 8; ks++) {
            float4 p4 = *(const float4*)(pf + ((bb * 2 + hh) * 8 + ks) * 128 + lane * 4);
            unsigned ph[4], pl[4];
            split_tf32(p4.x, ph[0], pl[0]);
            split_tf32(p4.y, ph[1], pl[1]);
            split_tf32(p4.z, ph[2], pl[2]);
            split_tf32(p4.w, ph[3], pl[3]);
#pragma unroll
            for (int ct = 0; ct < 4; ct++) {
                float2 vv = *(const float2*)(vf + ((bb * 4 + ct) * 8 + ks) * 64 + lane * 2);
                unsigned vh0, vl0, vh1, vl1;
                split_tf32(vv.x, vh0, vl0);
                split_tf32(vv.y, vh1, vl1);
                mma_tf32(yacc[ct], ph, vh0, vh1);
                mma_tf32(yacc[ct], ph, vl0, vl1);
                mma_tf32(yacc[ct], pl, vh0, vh1);
            }
        }
    }

    // ---- write y[bb][n][c] ----
    {
        float* yb = gY + bb * (NFLAT * CH) + (n0 + hh * 16) * CH;
#pragma unroll
        for (int ct = 0; ct < 4; ct++) {
            *(float2*)(yb +  g      * CH + ct * 8 + tg * 2) =
                make_float2(yacc[ct][0], yacc[ct][1]);
            *(float2*)(yb + (g + 8) * CH + ct * 8 + tg * 2) =
                make_float2(yacc[ct][2], yacc[ct][3]);
        }
    }
}

// ---------------------------------------------------------------------------
// Kernel 3: final 1x1 conv (32->64). Output channels split across blockIdx.y.
// ---------------------------------------------------------------------------
__global__ __launch_bounds__(256) void outconv_kernel(
    const float* __restrict__ w4, const float* __restrict__ b4,
    float* __restrict__ out)
{
    __shared__ float ws[32 * CH];
    __shared__ float bs[32];
    int t = threadIdx.x;
    int cob = blockIdx.y * 32;
    for (int i = t; i < 32 * CH; i += 256) ws[i] = w4[cob * CH + i];
    if (t < 32) bs[t] = b4[cob + t];
    __syncthreads();

    int idx = blockIdx.x * 256 + t;
    int b = idx >> 12, hw = idx & 4095;
    const float* yp = gY + b * (CH * NFLAT) + hw;   // y2[b][ci][hw]

    float acc[32];
#pragma unroll
    for (int co = 0; co < 32; co++) acc[co] = bs[co];

#pragma unroll 8
    for (int ci = 0; ci < CH; ci++) {
        float yv = yp[ci * NFLAT];
#pragma unroll
        for (int co = 0; co < 32; co++) acc[co] += ws[co * CH + ci] * yv;
    }

    float* op = out + b * (CIN * NFLAT) + cob * NFLAT + hw;
#pragma unroll
    for (int co = 0; co < 32; co++) op[co * NFLAT] = acc[co];
}

// ---------------------------------------------------------------------------
extern "C" void kernel_launch(void* const* d_in, const int* in_sizes, int n_in,
                              void* d_out, int out_size)
{
    const float* x  = (const float*)d_in[0];
    const float* w1 = (const float*)d_in[1];
    const float* b1 = (const float*)d_in[2];
    const float* w2 = (const float*)d_in[3];
    const float* b2 = (const float*)d_in[4];
    const float* w3 = (const float*)d_in[5];
    const float* b3 = (const float*)d_in[6];
    const float* w4 = (const float*)d_in[7];
    const float* b4 = (const float*)d_in[8];
    float* out = (float*)d_out;

    cudaFuncSetAttribute(attn_kernel,
                         cudaFuncAttributeMaxDynamicSharedMemorySize, SM_BYTES);

    qkv_kernel<<<dim3(64, 3, 2), 256>>>(x, w1, b1, w2, b2, w3, b3);
    attn_kernel<<<128, 256, SM_BYTES>>>();
    outconv_kernel<<<dim3(64, 2), 256>>>(w4, b4, out);
}